// round 3
// baseline (speedup 1.0000x reference)
#include <cuda_runtime.h>
#include <stdint.h>

#define D 8
#define DD 64

// Grid-stride float4 zero fill: pure HBM-write-bound.
__global__ void zero_kernel(float4* __restrict__ out, size_t n4) {
    size_t i = (size_t)blockIdx.x * blockDim.x + threadIdx.x;
    size_t stride = (size_t)gridDim.x * blockDim.x;
    const float4 z = make_float4(0.f, 0.f, 0.f, 0.f);
    for (; i < n4; i += stride) out[i] = z;
}

// 4 edges per 256-thread block; 64 threads per edge (one per output element).
// Duplicate (src,dst) edges write identical values -> racing writes are benign
// and deterministic (byte-identical), matching the reference's indexed assign.
__global__ void scatter_kernel(const float* __restrict__ x,
                               const int* __restrict__ ei,
                               const float* __restrict__ W,
                               float* __restrict__ out,
                               int e, int n) {
    __shared__ float sW[DD * D];     // 64x8 weight, row-major [out,in]
    __shared__ float sxin[4][D];     // |x_src - x_dst| per edge slot
    __shared__ int ssrc[4], sdst[4];

    int t = threadIdx.x;
    for (int i = t; i < DD * D; i += blockDim.x) sW[i] = W[i];

    int g = t >> 6;       // edge slot in block (0..3)
    int k = t & 63;       // output element (0..63)
    int edge = blockIdx.x * 4 + g;

    if (edge < e) {
        int src = ei[edge];
        int dst = ei[e + edge];
        if (k == 0) { ssrc[g] = src; sdst[g] = dst; }
        if (k < D) sxin[g][k] = fabsf(x[src * D + k] - x[dst * D + k]);
    }
    __syncthreads();

    if (edge < e) {
        float acc = 0.0f;
        #pragma unroll
        for (int d = 0; d < D; d++) acc += sW[k * D + d] * sxin[g][d];
        out[((long long)ssrc[g] * n + sdst[g]) * DD + k] = acc;
    }
}

extern "C" void kernel_launch(void* const* d_in, const int* in_sizes, int n_in,
                              void* d_out, int out_size) {
    const float* x  = (const float*)d_in[0];
    const int*   ei = (const int*)d_in[1];    // int64 in reference, int32 here
    const float* W  = (const float*)d_in[2];
    float* out = (float*)d_out;

    int n = in_sizes[0] / D;     // 1024
    int e = in_sizes[1] / 2;     // 32768

    // 1) Zero the 256 MB output with a kernel (memset nodes are not
    //    capturable on this allocation's address space).
    size_t n4 = (size_t)out_size / 4;   // out_size divisible by 4 (n*n*64)
    zero_kernel<<<4096, 256>>>((float4*)out, n4);

    // 2) Compute per-edge W @ |x_i - x_j| and scatter 64 floats per edge.
    scatter_kernel<<<(e + 3) / 4, 256>>>(x, ei, W, out, e, n);
}